// round 8
// baseline (speedup 1.0000x reference)
#include <cuda_runtime.h>

// CapsuleLinear k-means routing, collapsed to 8-vector state y per o:
//   v = G y / sqrt(y^T G y) * log2(e),  G = W^T W
//   l_n = x_n . v  (base-2 logit);  e = 2^l = exp(x_n . v_orig)
//   y' = sum_n e_n x_n ; last iter: sum = sum_n e_n
//   out = (W y')/sum ; probs = e/sum
// TPB=128, 9 rows/thread register-resident, packed f32x2 FMA.
// All-warp redundant centroid step + double-buffered reduction scratch
// -> exactly ONE __syncthreads per routing iteration, no serial warp.

#define TPB   128
#define NWARP 4
#define ROWS  9
#define OPB   4
#define NB    64
#define NN    1152
#define NO    64
#define NL    16
#define NI    8
#define NITER 3
#define LOG2E 1.4426950408889634f

typedef unsigned long long u64;

__device__ __forceinline__ u64 pack2(float x, float y) {
    u64 r; asm("mov.b64 %0, {%1, %2};" : "=l"(r) : "f"(x), "f"(y)); return r;
}
__device__ __forceinline__ void unpack2(u64 v, float& x, float& y) {
    asm("mov.b64 {%0, %1}, %2;" : "=f"(x), "=f"(y) : "l"(v));
}
__device__ __forceinline__ u64 ffma2(u64 a, u64 b, u64 c) {
    u64 d; asm("fma.rn.f32x2 %0, %1, %2, %3;" : "=l"(d) : "l"(a), "l"(b), "l"(c)); return d;
}
__device__ __forceinline__ u64 fadd2(u64 a, u64 b) {
    u64 d; asm("add.rn.f32x2 %0, %1, %2;" : "=l"(d) : "l"(a), "l"(b)); return d;
}
__device__ __forceinline__ float ex2(float x) {
    float r; asm("ex2.approx.ftz.f32 %0, %1;" : "=f"(r) : "f"(x)); return r;
}

// Reduce 8 per-lane values across the warp in 9 shfl; lanes 0..7 end up
// holding the warp total of component comp(lane).
__device__ __forceinline__ float warpReduce8(const float* v, int lane, int& comp) {
    const unsigned FM = 0xffffffffu;
    bool h1 = lane & 1;
    float a0 = (h1 ? v[4] : v[0]) + __shfl_xor_sync(FM, h1 ? v[0] : v[4], 1);
    float a1 = (h1 ? v[5] : v[1]) + __shfl_xor_sync(FM, h1 ? v[1] : v[5], 1);
    float a2 = (h1 ? v[6] : v[2]) + __shfl_xor_sync(FM, h1 ? v[2] : v[6], 1);
    float a3 = (h1 ? v[7] : v[3]) + __shfl_xor_sync(FM, h1 ? v[3] : v[7], 1);
    bool h2 = lane & 2;
    float b0 = (h2 ? a2 : a0) + __shfl_xor_sync(FM, h2 ? a0 : a2, 2);
    float b1 = (h2 ? a3 : a1) + __shfl_xor_sync(FM, h2 ? a1 : a3, 2);
    bool h4 = lane & 4;
    float c  = (h4 ? b1 : b0) + __shfl_xor_sync(FM, h4 ? b0 : b1, 4);
    c += __shfl_xor_sync(FM, c, 8);
    c += __shfl_xor_sync(FM, c, 16);
    comp = (lane & 1) * 4 + (lane & 2) + ((lane >> 2) & 1);
    return c;
}

struct Smem {
    float sW[OPB][NL][NI];
    float sG[OPB][NI][NI];
    float sred[2][OPB][NWARP][NI + 1];   // double-buffered partials
    float s_v[OPB][NI];
    float sY[OPB][NI];
    float s_invs[OPB];
    float se[OPB * NN];
};

__global__ __launch_bounds__(TPB, 5) void caps_kernel(
    const float* __restrict__ x,     // [NB, NN, NI]
    const float* __restrict__ w,     // [NO, NL, NI]
    float* __restrict__ outbuf)      // [NB*NO*NL] out, then [NB*NO*NN] probs
{
    float* out_ptr   = outbuf;
    float* probs_ptr = outbuf + NB * NO * NL;

    const int tid  = threadIdx.x;
    const int lane = tid & 31;
    const int wid  = tid >> 5;
    const int b    = blockIdx.x >> 4;
    const int og   = blockIdx.x & 15;

    __shared__ Smem sm;

    // ---- x rows into packed registers ----
    u64 xr[ROWS][4];
    {
        const float4* xb4 = reinterpret_cast<const float4*>(x + (size_t)b * NN * NI);
#pragma unroll
        for (int r = 0; r < ROWS; r++) {
            int n = r * TPB + tid;
            float4 a0 = xb4[2 * n];
            float4 a1 = xb4[2 * n + 1];
            xr[r][0] = pack2(a0.x, a0.y); xr[r][1] = pack2(a0.z, a0.w);
            xr[r][2] = pack2(a1.x, a1.y); xr[r][3] = pack2(a1.z, a1.w);
        }
    }

    // ---- weights: 512 floats = 128 float4 ----
    {
        const float4* wsrc = reinterpret_cast<const float4*>(w + (size_t)og * OPB * NL * NI);
        reinterpret_cast<float4*>(sm.sW)[tid] = wsrc[tid];
    }
    __syncthreads();   // sW ready

    // ---- G = W^T W (256 entries, 2 per thread) ----
#pragma unroll
    for (int k = 0; k < 2; k++) {
        int e2 = tid + k * TPB;
        int o = e2 >> 6, i = (e2 >> 3) & 7, jj = e2 & 7;
        float acc = 0.f;
#pragma unroll
        for (int l = 0; l < NL; l++) acc += sm.sW[o][l][i] * sm.sW[o][l][jj];
        sm.sG[o][i][jj] = acc;
    }

    // ---- s0 partials: per-warp sum of x rows -> sred[0][0][wid] ----
    {
        u64 a0 = xr[0][0], a1 = xr[0][1], a2 = xr[0][2], a3 = xr[0][3];
#pragma unroll
        for (int r = 1; r < ROWS; r++) {
            a0 = fadd2(a0, xr[r][0]); a1 = fadd2(a1, xr[r][1]);
            a2 = fadd2(a2, xr[r][2]); a3 = fadd2(a3, xr[r][3]);
        }
        float sv[8];
        unpack2(a0, sv[0], sv[1]); unpack2(a1, sv[2], sv[3]);
        unpack2(a2, sv[4], sv[5]); unpack2(a3, sv[6], sv[7]);
        int comp; float red = warpReduce8(sv, lane, comp);
        if (lane < 8) sm.sred[0][0][wid][comp] = red;
    }
    __syncthreads();   // sG + s0 partials ready

#pragma unroll
    for (int it = 0; it < NITER; ++it) {
        const bool last = (it == NITER - 1);
        const int rb = it & 1;        // read buffer (iter0 reads s0 in buf0)
        const int wb = rb ^ 1;        // write buffer
        const unsigned FM = 0xffffffffu;

        // -- ALL warps redundantly: finalize y, v = G y * rsqrt(y^T G y) * log2e --
        {
            int o = lane >> 3, i = lane & 7;
            int osrc = (it == 0) ? 0 : o;   // iter0: all o share y0 = sum x
            float yi = sm.sred[rb][osrc][0][i] + sm.sred[rb][osrc][1][i]
                     + sm.sred[rb][osrc][2][i] + sm.sred[rb][osrc][3][i];
            float g = 0.f;
            int gbase = lane & 24;
#pragma unroll
            for (int j = 0; j < NI; j++)
                g = fmaf(sm.sG[o][i][j], __shfl_sync(FM, yi, gbase | j), g);
            float p = yi * g;
            p += __shfl_xor_sync(FM, p, 1);
            p += __shfl_xor_sync(FM, p, 2);
            p += __shfl_xor_sync(FM, p, 4);
            // all warps write identical values -> benign
            sm.s_v[o][i] = g * rsqrtf(p) * LOG2E;
            __syncwarp();
        }

        // -- per-o mainloop --
#pragma unroll
        for (int o = 0; o < OPB; o++) {
            const float4* vpp = reinterpret_cast<const float4*>(sm.s_v[o]);
            float4 vA = vpp[0], vB = vpp[1];
            u64 v0 = pack2(vA.x, vA.y), v1 = pack2(vA.z, vA.w);
            u64 v2 = pack2(vB.x, vB.y), v3 = pack2(vB.z, vB.w);
            u64 py0 = 0ull, py1 = 0ull, py2 = 0ull, py3 = 0ull;
            float psum = 0.f;
#pragma unroll
            for (int r = 0; r < ROWS; r++) {
                u64 acc = ffma2(xr[r][0], v0, 0ull);
                acc = ffma2(xr[r][1], v1, acc);
                acc = ffma2(xr[r][2], v2, acc);
                acc = ffma2(xr[r][3], v3, acc);
                float lx, ly; unpack2(acc, lx, ly);
                float ev = ex2(lx + ly);
                if (last) { sm.se[o * NN + r * TPB + tid] = ev; psum += ev; }
                u64 ev2 = pack2(ev, ev);
                py0 = ffma2(ev2, xr[r][0], py0);
                py1 = ffma2(ev2, xr[r][1], py1);
                py2 = ffma2(ev2, xr[r][2], py2);
                py3 = ffma2(ev2, xr[r][3], py3);
            }
            float pv[8];
            unpack2(py0, pv[0], pv[1]); unpack2(py1, pv[2], pv[3]);
            unpack2(py2, pv[4], pv[5]); unpack2(py3, pv[6], pv[7]);
            int comp; float red = warpReduce8(pv, lane, comp);
            if (lane < 8) sm.sred[wb][o][wid][comp] = red;
            if (last) {
                psum += __shfl_xor_sync(FM, psum, 1);
                psum += __shfl_xor_sync(FM, psum, 2);
                psum += __shfl_xor_sync(FM, psum, 4);
                psum += __shfl_xor_sync(FM, psum, 8);
                psum += __shfl_xor_sync(FM, psum, 16);
                if (lane == 0) sm.sred[wb][o][wid][NI] = psum;
            }
        }
        __syncthreads();   // ONE barrier per iteration
    }

    // ---- finalize y, 1/sum (last write buffer: wb of it=2 -> buf 1) ----
    if (tid < OPB * (NI + 1)) {
        int o = tid / (NI + 1), cmp = tid % (NI + 1);
        float acc = sm.sred[1][o][0][cmp] + sm.sred[1][o][1][cmp]
                  + sm.sred[1][o][2][cmp] + sm.sred[1][o][3][cmp];
        if (cmp < NI) sm.sY[o][cmp] = acc;
        else          sm.s_invs[o] = 1.0f / acc;
    }
    __syncthreads();

    // ---- out = (W y)/sum ----
    if (tid < OPB * NL) {
        int o = tid >> 4, l = tid & 15;
        float acc = 0.f;
#pragma unroll
        for (int i = 0; i < NI; i++) acc = fmaf(sm.sW[o][l][i], sm.sY[o][i], acc);
        out_ptr[((size_t)b * NO + og * OPB + o) * NL + l] = acc * sm.s_invs[o];
    }

    // ---- probs = e/sum (288 float4 per o over 128 threads) ----
    {
        float4* pb0 = reinterpret_cast<float4*>(probs_ptr + ((size_t)b * NO + og * OPB) * NN);
        const float4* sp0 = reinterpret_cast<const float4*>(sm.se);
#pragma unroll
        for (int o = 0; o < OPB; o++) {
            float inv = sm.s_invs[o];
            float4* pb = pb0 + o * (NN / 4);
            const float4* sp = sp0 + o * (NN / 4);
            float4 q0 = sp[tid];
            q0.x *= inv; q0.y *= inv; q0.z *= inv; q0.w *= inv;
            pb[tid] = q0;
            float4 q1 = sp[TPB + tid];
            q1.x *= inv; q1.y *= inv; q1.z *= inv; q1.w *= inv;
            pb[TPB + tid] = q1;
            if (tid < 32) {
                float4 q2 = sp[2 * TPB + tid];
                q2.x *= inv; q2.y *= inv; q2.z *= inv; q2.w *= inv;
                pb[2 * TPB + tid] = q2;
            }
        }
    }
}

extern "C" void kernel_launch(void* const* d_in, const int* in_sizes, int n_in,
                              void* d_out, int out_size) {
    const float* x = (const float*)d_in[0];   // [64,1152,8]
    const float* w = (const float*)d_in[1];   // [64,16,8]
    float* out = (float*)d_out;
    (void)in_sizes; (void)n_in; (void)out_size;
    dim3 grid(NB * (NO / OPB));               // 1024 blocks
    caps_kernel<<<grid, TPB>>>(x, w, out);
}

// round 10
// speedup vs baseline: 1.4312x; 1.4312x over previous
#include <cuda_runtime.h>

// CapsuleLinear k-means routing, collapsed to 8-vector state y per o:
//   v = G y / sqrt(y^T G y) * log2(e),  G = W^T W
//   l_n = x_n . v  (base-2 logit);  e = 2^l = exp(x_n . v_orig)
//   y' = sum_n e_n x_n ; last iter: sum = sum_n e_n
//   out = (W y')/sum ; probs = e/sum
// TPB=128, 9 rows/thread register-resident, packed f32x2 FMA.
// All-warp redundant centroid step + double-buffered reduction scratch
// -> exactly ONE __syncthreads per routing iteration, no serial warp.
// (Resubmission of R8 to disambiguate bench anomaly vs ncu improvement.)

#define TPB   128
#define NWARP 4
#define ROWS  9
#define OPB   4
#define NB    64
#define NN    1152
#define NO    64
#define NL    16
#define NI    8
#define NITER 3
#define LOG2E 1.4426950408889634f

typedef unsigned long long u64;

__device__ __forceinline__ u64 pack2(float x, float y) {
    u64 r; asm("mov.b64 %0, {%1, %2};" : "=l"(r) : "f"(x), "f"(y)); return r;
}
__device__ __forceinline__ void unpack2(u64 v, float& x, float& y) {
    asm("mov.b64 {%0, %1}, %2;" : "=f"(x), "=f"(y) : "l"(v));
}
__device__ __forceinline__ u64 ffma2(u64 a, u64 b, u64 c) {
    u64 d; asm("fma.rn.f32x2 %0, %1, %2, %3;" : "=l"(d) : "l"(a), "l"(b), "l"(c)); return d;
}
__device__ __forceinline__ u64 fadd2(u64 a, u64 b) {
    u64 d; asm("add.rn.f32x2 %0, %1, %2;" : "=l"(d) : "l"(a), "l"(b)); return d;
}
__device__ __forceinline__ float ex2(float x) {
    float r; asm("ex2.approx.ftz.f32 %0, %1;" : "=f"(r) : "f"(x)); return r;
}

// Reduce 8 per-lane values across the warp in 9 shfl; lanes 0..7 end up
// holding the warp total of component comp(lane).
__device__ __forceinline__ float warpReduce8(const float* v, int lane, int& comp) {
    const unsigned FM = 0xffffffffu;
    bool h1 = lane & 1;
    float a0 = (h1 ? v[4] : v[0]) + __shfl_xor_sync(FM, h1 ? v[0] : v[4], 1);
    float a1 = (h1 ? v[5] : v[1]) + __shfl_xor_sync(FM, h1 ? v[1] : v[5], 1);
    float a2 = (h1 ? v[6] : v[2]) + __shfl_xor_sync(FM, h1 ? v[2] : v[6], 1);
    float a3 = (h1 ? v[7] : v[3]) + __shfl_xor_sync(FM, h1 ? v[3] : v[7], 1);
    bool h2 = lane & 2;
    float b0 = (h2 ? a2 : a0) + __shfl_xor_sync(FM, h2 ? a0 : a2, 2);
    float b1 = (h2 ? a3 : a1) + __shfl_xor_sync(FM, h2 ? a1 : a3, 2);
    bool h4 = lane & 4;
    float c  = (h4 ? b1 : b0) + __shfl_xor_sync(FM, h4 ? b0 : b1, 4);
    c += __shfl_xor_sync(FM, c, 8);
    c += __shfl_xor_sync(FM, c, 16);
    comp = (lane & 1) * 4 + (lane & 2) + ((lane >> 2) & 1);
    return c;
}

struct Smem {
    float sW[OPB][NL][NI];
    float sG[OPB][NI][NI];
    float sred[2][OPB][NWARP][NI + 1];   // double-buffered partials
    float s_v[OPB][NI];
    float sY[OPB][NI];
    float s_invs[OPB];
    float se[OPB * NN];
};

__global__ __launch_bounds__(TPB, 5) void caps_kernel(
    const float* __restrict__ x,     // [NB, NN, NI]
    const float* __restrict__ w,     // [NO, NL, NI]
    float* __restrict__ outbuf)      // [NB*NO*NL] out, then [NB*NO*NN] probs
{
    float* out_ptr   = outbuf;
    float* probs_ptr = outbuf + NB * NO * NL;

    const int tid  = threadIdx.x;
    const int lane = tid & 31;
    const int wid  = tid >> 5;
    const int b    = blockIdx.x >> 4;
    const int og   = blockIdx.x & 15;

    __shared__ Smem sm;

    // ---- x rows into packed registers ----
    u64 xr[ROWS][4];
    {
        const float4* xb4 = reinterpret_cast<const float4*>(x + (size_t)b * NN * NI);
#pragma unroll
        for (int r = 0; r < ROWS; r++) {
            int n = r * TPB + tid;
            float4 a0 = xb4[2 * n];
            float4 a1 = xb4[2 * n + 1];
            xr[r][0] = pack2(a0.x, a0.y); xr[r][1] = pack2(a0.z, a0.w);
            xr[r][2] = pack2(a1.x, a1.y); xr[r][3] = pack2(a1.z, a1.w);
        }
    }

    // ---- weights: 512 floats = 128 float4 ----
    {
        const float4* wsrc = reinterpret_cast<const float4*>(w + (size_t)og * OPB * NL * NI);
        reinterpret_cast<float4*>(sm.sW)[tid] = wsrc[tid];
    }
    __syncthreads();   // sW ready

    // ---- G = W^T W (256 entries, 2 per thread) ----
#pragma unroll
    for (int k = 0; k < 2; k++) {
        int e2 = tid + k * TPB;
        int o = e2 >> 6, i = (e2 >> 3) & 7, jj = e2 & 7;
        float acc = 0.f;
#pragma unroll
        for (int l = 0; l < NL; l++) acc += sm.sW[o][l][i] * sm.sW[o][l][jj];
        sm.sG[o][i][jj] = acc;
    }

    // ---- s0 partials: per-warp sum of x rows -> sred[0][0][wid] ----
    {
        u64 a0 = xr[0][0], a1 = xr[0][1], a2 = xr[0][2], a3 = xr[0][3];
#pragma unroll
        for (int r = 1; r < ROWS; r++) {
            a0 = fadd2(a0, xr[r][0]); a1 = fadd2(a1, xr[r][1]);
            a2 = fadd2(a2, xr[r][2]); a3 = fadd2(a3, xr[r][3]);
        }
        float sv[8];
        unpack2(a0, sv[0], sv[1]); unpack2(a1, sv[2], sv[3]);
        unpack2(a2, sv[4], sv[5]); unpack2(a3, sv[6], sv[7]);
        int comp; float red = warpReduce8(sv, lane, comp);
        if (lane < 8) sm.sred[0][0][wid][comp] = red;
    }
    __syncthreads();   // sG + s0 partials ready

#pragma unroll
    for (int it = 0; it < NITER; ++it) {
        const bool last = (it == NITER - 1);
        const int rb = it & 1;        // read buffer (iter0 reads s0 in buf0)
        const int wb = rb ^ 1;        // write buffer
        const unsigned FM = 0xffffffffu;

        // -- ALL warps redundantly: finalize y, v = G y * rsqrt(y^T G y) * log2e --
        {
            int o = lane >> 3, i = lane & 7;
            int osrc = (it == 0) ? 0 : o;   // iter0: all o share y0 = sum x
            float yi = sm.sred[rb][osrc][0][i] + sm.sred[rb][osrc][1][i]
                     + sm.sred[rb][osrc][2][i] + sm.sred[rb][osrc][3][i];
            float g = 0.f;
            int gbase = lane & 24;
#pragma unroll
            for (int j = 0; j < NI; j++)
                g = fmaf(sm.sG[o][i][j], __shfl_sync(FM, yi, gbase | j), g);
            float p = yi * g;
            p += __shfl_xor_sync(FM, p, 1);
            p += __shfl_xor_sync(FM, p, 2);
            p += __shfl_xor_sync(FM, p, 4);
            // all warps write identical values -> benign
            sm.s_v[o][i] = g * rsqrtf(p) * LOG2E;
            __syncwarp();
        }

        // -- per-o mainloop --
#pragma unroll
        for (int o = 0; o < OPB; o++) {
            const float4* vpp = reinterpret_cast<const float4*>(sm.s_v[o]);
            float4 vA = vpp[0], vB = vpp[1];
            u64 v0 = pack2(vA.x, vA.y), v1 = pack2(vA.z, vA.w);
            u64 v2 = pack2(vB.x, vB.y), v3 = pack2(vB.z, vB.w);
            u64 py0 = 0ull, py1 = 0ull, py2 = 0ull, py3 = 0ull;
            float psum = 0.f;
#pragma unroll
            for (int r = 0; r < ROWS; r++) {
                u64 acc = ffma2(xr[r][0], v0, 0ull);
                acc = ffma2(xr[r][1], v1, acc);
                acc = ffma2(xr[r][2], v2, acc);
                acc = ffma2(xr[r][3], v3, acc);
                float lx, ly; unpack2(acc, lx, ly);
                float ev = ex2(lx + ly);
                if (last) { sm.se[o * NN + r * TPB + tid] = ev; psum += ev; }
                u64 ev2 = pack2(ev, ev);
                py0 = ffma2(ev2, xr[r][0], py0);
                py1 = ffma2(ev2, xr[r][1], py1);
                py2 = ffma2(ev2, xr[r][2], py2);
                py3 = ffma2(ev2, xr[r][3], py3);
            }
            float pv[8];
            unpack2(py0, pv[0], pv[1]); unpack2(py1, pv[2], pv[3]);
            unpack2(py2, pv[4], pv[5]); unpack2(py3, pv[6], pv[7]);
            int comp; float red = warpReduce8(pv, lane, comp);
            if (lane < 8) sm.sred[wb][o][wid][comp] = red;
            if (last) {
                psum += __shfl_xor_sync(FM, psum, 1);
                psum += __shfl_xor_sync(FM, psum, 2);
                psum += __shfl_xor_sync(FM, psum, 4);
                psum += __shfl_xor_sync(FM, psum, 8);
                psum += __shfl_xor_sync(FM, psum, 16);
                if (lane == 0) sm.sred[wb][o][wid][NI] = psum;
            }
        }
        __syncthreads();   // ONE barrier per iteration
    }

    // ---- finalize y, 1/sum (last write buffer: wb of it=2 -> buf 1) ----
    if (tid < OPB * (NI + 1)) {
        int o = tid / (NI + 1), cmp = tid % (NI + 1);
        float acc = sm.sred[1][o][0][cmp] + sm.sred[1][o][1][cmp]
                  + sm.sred[1][o][2][cmp] + sm.sred[1][o][3][cmp];
        if (cmp < NI) sm.sY[o][cmp] = acc;
        else          sm.s_invs[o] = 1.0f / acc;
    }
    __syncthreads();

    // ---- out = (W y)/sum ----
    if (tid < OPB * NL) {
        int o = tid >> 4, l = tid & 15;
        float acc = 0.f;
#pragma unroll
        for (int i = 0; i < NI; i++) acc = fmaf(sm.sW[o][l][i], sm.sY[o][i], acc);
        out_ptr[((size_t)b * NO + og * OPB + o) * NL + l] = acc * sm.s_invs[o];
    }

    // ---- probs = e/sum (288 float4 per o over 128 threads) ----
    {
        float4* pb0 = reinterpret_cast<float4*>(probs_ptr + ((size_t)b * NO + og * OPB) * NN);
        const float4* sp0 = reinterpret_cast<const float4*>(sm.se);
#pragma unroll
        for (int o = 0; o < OPB; o++) {
            float inv = sm.s_invs[o];
            float4* pb = pb0 + o * (NN / 4);
            const float4* sp = sp0 + o * (NN / 4);
            float4 q0 = sp[tid];
            q0.x *= inv; q0.y *= inv; q0.z *= inv; q0.w *= inv;
            pb[tid] = q0;
            float4 q1 = sp[TPB + tid];
            q1.x *= inv; q1.y *= inv; q1.z *= inv; q1.w *= inv;
            pb[TPB + tid] = q1;
            if (tid < 32) {
                float4 q2 = sp[2 * TPB + tid];
                q2.x *= inv; q2.y *= inv; q2.z *= inv; q2.w *= inv;
                pb[2 * TPB + tid] = q2;
            }
        }
    }
}

extern "C" void kernel_launch(void* const* d_in, const int* in_sizes, int n_in,
                              void* d_out, int out_size) {
    const float* x = (const float*)d_in[0];   // [64,1152,8]
    const float* w = (const float*)d_in[1];   // [64,16,8]
    float* out = (float*)d_out;
    (void)in_sizes; (void)n_in; (void)out_size;
    dim3 grid(NB * (NO / OPB));               // 1024 blocks
    caps_kernel<<<grid, TPB>>>(x, w, out);
}